// round 9
// baseline (speedup 1.0000x reference)
#include <cuda_runtime.h>

#define N 8192
#define THREADS 256
#define ROWS_PER_BLOCK 8
#define KCHUNK 2048
#define NCHUNK (N / KCHUNK)                 // 4
#define ROWGROUPS (N / ROWS_PER_BLOCK)      // 1024
#define GRID (ROWGROUPS * NCHUNK)           // 4096
#define ITERS (KCHUNK / (32 * 4))           // 16 float4 iters per lane
#define CNT_TARGET (8 * NCHUNK)             // 32 arrivals per rowgroup

__device__ float g_part[NCHUNK * N];
__device__ unsigned int g_cnt[ROWGROUPS];   // zero-init; epilogue resets to 0

__device__ __forceinline__ float fast_tanh(float v)
{
    float o;
    asm("tanh.approx.f32 %0, %1;" : "=f"(o) : "f"(v));
    return o;
}

__device__ __forceinline__ void red_release_add(unsigned int* p, unsigned int v)
{
    asm volatile("red.release.gpu.global.add.u32 [%0], %1;"
                 :: "l"(p), "r"(v) : "memory");
}

__device__ __forceinline__ unsigned int ld_acquire(const unsigned int* p)
{
    unsigned int v;
    asm volatile("ld.acquire.gpu.global.u32 %0, [%1];"
                 : "=r"(v) : "l"(p) : "memory");
    return v;
}

__global__ __launch_bounds__(THREADS) void gemv_partial_kernel(
    const float* __restrict__ y,
    const float* __restrict__ W)
{
    __shared__ float r_s[KCHUNK];  // 8 KB

    const int tid   = threadIdx.x;
    const int bx    = blockIdx.x;
    const int chunk = bx >> 10;          // bx / ROWGROUPS (chunk-major)
    const int rowg  = bx & (ROWGROUPS - 1);
    const int col0  = chunk * KCHUNK;

    // Stage r-chunk with single-instruction MUFU tanh.
    {
        const float4* ysrc = reinterpret_cast<const float4*>(y + col0);
        float4* rdst = reinterpret_cast<float4*>(r_s);
        #pragma unroll
        for (int i = tid; i < KCHUNK / 4; i += THREADS) {
            float4 v = ysrc[i];
            float4 t;
            t.x = fast_tanh(v.x); t.y = fast_tanh(v.y);
            t.z = fast_tanh(v.z); t.w = fast_tanh(v.w);
            rdst[i] = t;
        }
    }
    __syncthreads();

    // Let the dependent epilogue begin launching while we stream W.
    cudaTriggerProgrammaticLaunchCompletion();

    const int warp = tid >> 5;
    const int lane = tid & 31;
    const int row  = rowg * ROWS_PER_BLOCK + warp;

    const float4* __restrict__ Wrow =
        reinterpret_cast<const float4*>(W + (size_t)row * N + col0);
    const float4* rs4 = reinterpret_cast<const float4*>(r_s);

    float a0 = 0.f, a1 = 0.f, a2 = 0.f, a3 = 0.f;
    #pragma unroll
    for (int i = 0; i < ITERS; i += 4) {
        float4 w0 = Wrow[(i + 0) * 32 + lane];
        float4 w1 = Wrow[(i + 1) * 32 + lane];
        float4 w2 = Wrow[(i + 2) * 32 + lane];
        float4 w3 = Wrow[(i + 3) * 32 + lane];
        float4 v0 = rs4[(i + 0) * 32 + lane];
        float4 v1 = rs4[(i + 1) * 32 + lane];
        float4 v2 = rs4[(i + 2) * 32 + lane];
        float4 v3 = rs4[(i + 3) * 32 + lane];
        a0 += w0.x * v0.x + w0.y * v0.y + w0.z * v0.z + w0.w * v0.w;
        a1 += w1.x * v1.x + w1.y * v1.y + w1.z * v1.z + w1.w * v1.w;
        a2 += w2.x * v2.x + w2.y * v2.y + w2.z * v2.z + w2.w * v2.w;
        a3 += w3.x * v3.x + w3.y * v3.y + w3.z * v3.z + w3.w * v3.w;
    }
    float acc = (a0 + a1) + (a2 + a3);

    #pragma unroll
    for (int off = 16; off > 0; off >>= 1)
        acc += __shfl_xor_sync(0xFFFFFFFFu, acc, off);

    if (lane == 0) {
        g_part[chunk * N + row] = acc;
        // Release: prior store visible to any acquirer of the counter.
        red_release_add(&g_cnt[rowg], 1u);
    }
}

__global__ void epilogue_kernel(
    const float* __restrict__ x,
    const float* __restrict__ y,
    float* __restrict__ out)
{
    const int i    = blockIdx.x * blockDim.x + threadIdx.x;  // element 0..8191
    const int rowg = i >> 3;           // 8 elements per rowgroup
    const int lane = threadIdx.x & 31;

    // Prefetch GEMV-independent inputs.
    float xi = x[i];
    float yi = y[i];

    // Lanes 0,8,16,24 poll their rowgroup's counter; others wait at syncwarp.
    if ((lane & 7) == 0) {
        while (ld_acquire(&g_cnt[rowg]) != CNT_TARGET)
            __nanosleep(64);
    }
    __syncwarp();

    float acc = g_part[0 * N + i] + g_part[1 * N + i]
              + g_part[2 * N + i] + g_part[3 * N + i];
    const float DT  = 1e-3f;
    const float TAU = 1e-2f;
    out[i] = yi + DT * ((-yi + acc + xi) / TAU);

    __syncwarp();
    // Reset counters for the next graph replay (graph edges order this
    // kernel's completion before the next replay's GEMV launch).
    if ((lane & 7) == 0)
        g_cnt[rowg] = 0u;
}

extern "C" void kernel_launch(void* const* d_in, const int* in_sizes, int n_in,
                              void* d_out, int out_size)
{
    const float* x = (const float*)d_in[0];
    const float* y = (const float*)d_in[1];
    const float* W = (const float*)d_in[2];
    float* out = (float*)d_out;

    gemv_partial_kernel<<<GRID, THREADS>>>(y, W);

    cudaLaunchConfig_t cfg = {};
    cfg.gridDim  = dim3(N / THREADS);   // 32
    cfg.blockDim = dim3(THREADS);
    cfg.stream   = 0;
    cudaLaunchAttribute attr[1];
    attr[0].id = cudaLaunchAttributeProgrammaticStreamSerialization;
    attr[0].val.programmaticStreamSerializationAllowed = 1;
    cfg.attrs    = attr;
    cfg.numAttrs = 1;
    cudaLaunchKernelEx(&cfg, epilogue_kernel, x, y, out);
}

// round 10
// speedup vs baseline: 1.0167x; 1.0167x over previous
#include <cuda_runtime.h>

#define N 8192
#define THREADS 256
#define ROWS_PER_BLOCK 8
#define KCHUNK 2048
#define NCHUNK (N / KCHUNK)                 // 4
#define ROWGROUPS (N / ROWS_PER_BLOCK)      // 1024
#define GRID (ROWGROUPS * NCHUNK)           // 4096
#define ITERS (KCHUNK / (32 * 4))           // 16 float4 iters per lane
#define ARRIVALS (8 * NCHUNK)               // 32 warp-arrivals per rowgroup

__device__ float g_part[NCHUNK * N];
__device__ unsigned int g_cnt[ROWGROUPS];   // zero-init; wraps back to 0 at 32

__device__ __forceinline__ float fast_tanh(float v)
{
    float o;
    asm("tanh.approx.f32 %0, %1;" : "=f"(o) : "f"(v));
    return o;
}

// atom.inc with acq_rel: returns old; new = (old >= b) ? 0 : old+1.
__device__ __forceinline__ unsigned int atom_inc_acqrel(unsigned int* p, unsigned int b)
{
    unsigned int old;
    asm volatile("atom.acq_rel.gpu.global.inc.u32 %0, [%1], %2;"
                 : "=r"(old) : "l"(p), "r"(b) : "memory");
    return old;
}

__global__ __launch_bounds__(THREADS) void gemv_fused_kernel(
    const float* __restrict__ x,
    const float* __restrict__ y,
    const float* __restrict__ W,
    float* __restrict__ out)
{
    __shared__ float r_s[KCHUNK];  // 8 KB

    const int tid   = threadIdx.x;
    const int bx    = blockIdx.x;
    const int chunk = bx >> 10;          // bx / ROWGROUPS (chunk-major)
    const int rowg  = bx & (ROWGROUPS - 1);
    const int col0  = chunk * KCHUNK;

    // Stage r-chunk with single-instruction MUFU tanh.
    {
        const float4* ysrc = reinterpret_cast<const float4*>(y + col0);
        float4* rdst = reinterpret_cast<float4*>(r_s);
        #pragma unroll
        for (int i = tid; i < KCHUNK / 4; i += THREADS) {
            float4 v = ysrc[i];
            float4 t;
            t.x = fast_tanh(v.x); t.y = fast_tanh(v.y);
            t.z = fast_tanh(v.z); t.w = fast_tanh(v.w);
            rdst[i] = t;
        }
    }
    __syncthreads();

    const int warp = tid >> 5;
    const int lane = tid & 31;
    const int row  = rowg * ROWS_PER_BLOCK + warp;

    const float4* __restrict__ Wrow =
        reinterpret_cast<const float4*>(W + (size_t)row * N + col0);
    const float4* rs4 = reinterpret_cast<const float4*>(r_s);

    float a0 = 0.f, a1 = 0.f, a2 = 0.f, a3 = 0.f;
    #pragma unroll
    for (int i = 0; i < ITERS; i += 4) {
        float4 w0 = Wrow[(i + 0) * 32 + lane];
        float4 w1 = Wrow[(i + 1) * 32 + lane];
        float4 w2 = Wrow[(i + 2) * 32 + lane];
        float4 w3 = Wrow[(i + 3) * 32 + lane];
        float4 v0 = rs4[(i + 0) * 32 + lane];
        float4 v1 = rs4[(i + 1) * 32 + lane];
        float4 v2 = rs4[(i + 2) * 32 + lane];
        float4 v3 = rs4[(i + 3) * 32 + lane];
        a0 += w0.x * v0.x + w0.y * v0.y + w0.z * v0.z + w0.w * v0.w;
        a1 += w1.x * v1.x + w1.y * v1.y + w1.z * v1.z + w1.w * v1.w;
        a2 += w2.x * v2.x + w2.y * v2.y + w2.z * v2.z + w2.w * v2.w;
        a3 += w3.x * v3.x + w3.y * v3.y + w3.z * v3.z + w3.w * v3.w;
    }
    float acc = (a0 + a1) + (a2 + a3);

    #pragma unroll
    for (int off = 16; off > 0; off >>= 1)
        acc += __shfl_xor_sync(0xFFFFFFFFu, acc, off);

    // Lane 0: publish partial (release), count arrival. 32nd arriver finalizes.
    unsigned int is_last = 0;
    if (lane == 0) {
        __stcg(&g_part[chunk * N + row], acc);
        is_last = (atom_inc_acqrel(&g_cnt[rowg], ARRIVALS - 1) == ARRIVALS - 1);
    }
    is_last = __shfl_sync(0xFFFFFFFFu, is_last, 0);

    if (is_last) {
        // This warp finalizes rowg's 8 outputs. lane -> (chunk = lane>>3, r = lane&7).
        const int c = lane >> 3;
        const int r = rowg * ROWS_PER_BLOCK + (lane & 7);
        float p = __ldcg(&g_part[c * N + r]);
        // Fold the 4 chunks (lanes differing in bits 3,4): fixed order, deterministic.
        p += __shfl_xor_sync(0xFFFFFFFFu, p, 8);
        p += __shfl_xor_sync(0xFFFFFFFFu, p, 16);
        if (lane < ROWS_PER_BLOCK) {
            const float DT  = 1e-3f;
            const float TAU = 1e-2f;
            float yr = y[r];
            out[r] = yr + DT * ((-yr + p + x[r]) / TAU);
        }
    }
}

extern "C" void kernel_launch(void* const* d_in, const int* in_sizes, int n_in,
                              void* d_out, int out_size)
{
    const float* x = (const float*)d_in[0];
    const float* y = (const float*)d_in[1];
    const float* W = (const float*)d_in[2];
    float* out = (float*)d_out;

    gemv_fused_kernel<<<GRID, THREADS>>>(x, y, W, out);
}

// round 11
// speedup vs baseline: 1.0226x; 1.0058x over previous
#include <cuda_runtime.h>

#define N 8192
#define THREADS 256
#define ROWS_PER_BLOCK 8
#define KCHUNK 2048
#define NCHUNK (N / KCHUNK)                 // 4
#define ROWGROUPS (N / ROWS_PER_BLOCK)      // 1024
#define GRID (ROWGROUPS * NCHUNK)           // 4096
#define ITERS (KCHUNK / (32 * 4))           // 16 float4 iters per lane

__device__ float g_part[NCHUNK * N];
__device__ unsigned int g_cnt[ROWGROUPS];   // zero-init; inc wraps 3 -> 0 (self-reset)

__device__ __forceinline__ float fast_tanh(float v)
{
    float o;
    asm("tanh.approx.f32 %0, %1;" : "=f"(o) : "f"(v));
    return o;
}

// atom.inc acq_rel: returns old; new = (old >= b) ? 0 : old+1.
__device__ __forceinline__ unsigned int atom_inc_acqrel(unsigned int* p, unsigned int b)
{
    unsigned int old;
    asm volatile("atom.acq_rel.gpu.global.inc.u32 %0, [%1], %2;"
                 : "=r"(old) : "l"(p), "r"(b) : "memory");
    return old;
}

__global__ __launch_bounds__(THREADS) void gemv_fused_kernel(
    const float* __restrict__ x,
    const float* __restrict__ y,
    const float* __restrict__ W,
    float* __restrict__ out)
{
    __shared__ float r_s[KCHUNK];  // 8 KB
    __shared__ unsigned int s_last;

    const int tid   = threadIdx.x;
    const int bx    = blockIdx.x;
    const int chunk = bx >> 10;          // bx / ROWGROUPS (chunk-major)
    const int rowg  = bx & (ROWGROUPS - 1);
    const int col0  = chunk * KCHUNK;

    // Stage r-chunk with single-instruction MUFU tanh.
    {
        const float4* ysrc = reinterpret_cast<const float4*>(y + col0);
        float4* rdst = reinterpret_cast<float4*>(r_s);
        #pragma unroll
        for (int i = tid; i < KCHUNK / 4; i += THREADS) {
            float4 v = ysrc[i];
            float4 t;
            t.x = fast_tanh(v.x); t.y = fast_tanh(v.y);
            t.z = fast_tanh(v.z); t.w = fast_tanh(v.w);
            rdst[i] = t;
        }
    }
    __syncthreads();

    const int warp = tid >> 5;
    const int lane = tid & 31;
    const int row  = rowg * ROWS_PER_BLOCK + warp;

    const float4* __restrict__ Wrow =
        reinterpret_cast<const float4*>(W + (size_t)row * N + col0);
    const float4* rs4 = reinterpret_cast<const float4*>(r_s);

    float a0 = 0.f, a1 = 0.f, a2 = 0.f, a3 = 0.f;
    float a4 = 0.f, a5 = 0.f, a6 = 0.f, a7 = 0.f;
    #pragma unroll
    for (int i = 0; i < ITERS; i += 8) {
        // Issue 8 independent LDG.128 back-to-back -> deep MLP per warp.
        float4 w0 = Wrow[(i + 0) * 32 + lane];
        float4 w1 = Wrow[(i + 1) * 32 + lane];
        float4 w2 = Wrow[(i + 2) * 32 + lane];
        float4 w3 = Wrow[(i + 3) * 32 + lane];
        float4 w4 = Wrow[(i + 4) * 32 + lane];
        float4 w5 = Wrow[(i + 5) * 32 + lane];
        float4 w6 = Wrow[(i + 6) * 32 + lane];
        float4 w7 = Wrow[(i + 7) * 32 + lane];
        // Consume with smem operands step by step (keeps r regs short-lived).
        float4 v;
        v = rs4[(i + 0) * 32 + lane];
        a0 += w0.x * v.x + w0.y * v.y + w0.z * v.z + w0.w * v.w;
        v = rs4[(i + 1) * 32 + lane];
        a1 += w1.x * v.x + w1.y * v.y + w1.z * v.z + w1.w * v.w;
        v = rs4[(i + 2) * 32 + lane];
        a2 += w2.x * v.x + w2.y * v.y + w2.z * v.z + w2.w * v.w;
        v = rs4[(i + 3) * 32 + lane];
        a3 += w3.x * v.x + w3.y * v.y + w3.z * v.z + w3.w * v.w;
        v = rs4[(i + 4) * 32 + lane];
        a4 += w4.x * v.x + w4.y * v.y + w4.z * v.z + w4.w * v.w;
        v = rs4[(i + 5) * 32 + lane];
        a5 += w5.x * v.x + w5.y * v.y + w5.z * v.z + w5.w * v.w;
        v = rs4[(i + 6) * 32 + lane];
        a6 += w6.x * v.x + w6.y * v.y + w6.z * v.z + w6.w * v.w;
        v = rs4[(i + 7) * 32 + lane];
        a7 += w7.x * v.x + w7.y * v.y + w7.z * v.z + w7.w * v.w;
    }
    float acc = ((a0 + a1) + (a2 + a3)) + ((a4 + a5) + (a6 + a7));

    #pragma unroll
    for (int off = 16; off > 0; off >>= 1)
        acc += __shfl_xor_sync(0xFFFFFFFFu, acc, off);

    if (lane == 0)
        __stcg(&g_part[chunk * N + row], acc);

    // One returning atomic per BLOCK (not per warp): syncthreads orders the
    // 8 partial stores before the release; release->acquire orders them
    // across blocks.
    __syncthreads();
    if (tid == 0)
        s_last = (atom_inc_acqrel(&g_cnt[rowg], NCHUNK - 1) == NCHUNK - 1) ? 1u : 0u;
    __syncthreads();

    if (s_last && warp == 0) {
        // 32 lanes: chunk c = lane>>3, row r = rowg*8 + (lane&7).
        const int r = rowg * ROWS_PER_BLOCK + (lane & 7);
        float p = __ldcg(&g_part[(lane >> 3) * N + r]);
        p += __shfl_xor_sync(0xFFFFFFFFu, p, 8);   // fold chunks, fixed order
        p += __shfl_xor_sync(0xFFFFFFFFu, p, 16);
        if (lane < ROWS_PER_BLOCK) {
            const float DT  = 1e-3f;
            const float TAU = 1e-2f;
            float yr = y[r];
            out[r] = yr + DT * ((-yr + p + x[r]) / TAU);
        }
    }
}

extern "C" void kernel_launch(void* const* d_in, const int* in_sizes, int n_in,
                              void* d_out, int out_size)
{
    const float* x = (const float*)d_in[0];
    const float* y = (const float*)d_in[1];
    const float* W = (const float*)d_in[2];
    float* out = (float*)d_out;

    gemv_fused_kernel<<<GRID, THREADS>>>(x, y, W, out);
}